// round 6
// baseline (speedup 1.0000x reference)
#include <cuda_runtime.h>
#include <math.h>
#include <stdint.h>

#define D_MODEL 1024
#define D_FF    4096
#define NUM_E   24
#define TOKENS  2048
#define CAP     512   // max tokens per expert (mean ~171, std ~13)

// ---------------- scratch (device globals: no allocation allowed) ----------------
__device__ int   g_cnt[NUM_E];
__device__ int   g_perm[NUM_E * CAP];        // token id per (expert, slot)
__device__ int   g_slot[TOKENS * 2];         // per (token, k): e*CAP+p or -1
__device__ float g_wgt[TOKENS * 2];          // per (token, k): softmax weight
__device__ float g_h[(size_t)NUM_E * CAP * D_FF];     // 192 MB: gelu(x·w1+b1)
__device__ float g_y[(size_t)NUM_E * CAP * D_MODEL];  //  48 MB: h·w2+b2

// ---------------- small kernels ----------------
__global__ void zero_cnt_kernel() {
    if (threadIdx.x < NUM_E) g_cnt[threadIdx.x] = 0;
}

// one block per token: scores = x·gate_w + gate_b, top-2, softmax, append to lists
__global__ void gate_kernel(const float* __restrict__ x,
                            const float* __restrict__ gw,
                            const float* __restrict__ gb) {
    __shared__ float sx[D_MODEL];
    __shared__ float sc[NUM_E];
    const int t = blockIdx.x;
    const float* xr = x + (size_t)t * D_MODEL;
    for (int i = threadIdx.x; i < D_MODEL; i += blockDim.x) sx[i] = xr[i];
    __syncthreads();

    const int lane = threadIdx.x & 31, warp = threadIdx.x >> 5;
    for (int e = warp; e < NUM_E; e += 4) {
        float s = 0.f;
        for (int d = lane; d < D_MODEL; d += 32) s += sx[d] * gw[d * NUM_E + e];
        #pragma unroll
        for (int o = 16; o; o >>= 1) s += __shfl_xor_sync(0xffffffffu, s, o);
        if (lane == 0) sc[e] = s + gb[e];
    }
    __syncthreads();

    if (threadIdx.x == 0) {
        int   i0 = 0; float v0 = sc[0];
        for (int e = 1; e < NUM_E; e++) if (sc[e] > v0) { v0 = sc[e]; i0 = e; }
        int   i1 = -1; float v1 = -3.4e38f;
        for (int e = 0; e < NUM_E; e++) if (e != i0 && sc[e] > v1) { v1 = sc[e]; i1 = e; }
        float w0 = 1.f / (1.f + expf(v1 - v0));   // softmax over (v0, v1), v0 >= v1
        int   ev[2] = { i0, i1 };
        float wv[2] = { w0, 1.f - w0 };
        #pragma unroll
        for (int k = 0; k < 2; k++) {
            int e = ev[k];
            int p = atomicAdd(&g_cnt[e], 1);
            if (p < CAP) {
                g_perm[e * CAP + p]  = t;
                g_slot[t * 2 + k]    = e * CAP + p;
                g_wgt [t * 2 + k]    = wv[k];
            } else {
                g_slot[t * 2 + k] = -1;
                g_wgt [t * 2 + k] = 0.f;
            }
        }
    }
}

// ---------------- tf32 mma helpers ----------------
__device__ __forceinline__ unsigned f2tf(float f) {
    unsigned r;
    asm("cvt.rna.tf32.f32 %0, %1;" : "=r"(r) : "f"(f));
    return r;
}
__device__ __forceinline__ void mma8(float* d, const unsigned* a, const unsigned* b) {
    asm volatile(
        "mma.sync.aligned.m16n8k8.row.col.f32.tf32.tf32.f32 "
        "{%0,%1,%2,%3},{%4,%5,%6,%7},{%8,%9},{%0,%1,%2,%3};\n"
        : "+f"(d[0]), "+f"(d[1]), "+f"(d[2]), "+f"(d[3])
        : "r"(a[0]), "r"(a[1]), "r"(a[2]), "r"(a[3]), "r"(b[0]), "r"(b[1]));
}

// ---------------- grouped GEMM (per-expert), 64x64x16 tiles, 2x2 warps ----------------
// GATHER=true : A rows gathered from x via g_perm, O = g_h, GELU epilogue  (GEMM1)
// GATHER=false: A rows = g_h contiguous per expert,  O = g_y, no act      (GEMM2)
template<int KD, int ND, bool GATHER, bool GELU_ACT>
__global__ __launch_bounds__(128)
void moe_gemm_kernel(const float* __restrict__ Ax,
                     const float* __restrict__ W,      // [E, KD, ND] row-major
                     const float* __restrict__ bias) { // [E, ND]
    const int e   = blockIdx.z;
    const int cnt = min(g_cnt[e], CAP);
    const int m0  = blockIdx.y * 64;
    if (m0 >= cnt) return;
    const int n0  = blockIdx.x * 64;

    const float* Abase = GATHER ? Ax : g_h;
    float*       Obase = GATHER ? g_h : g_y;

    // padded strides: frag loads hit 32 distinct banks; float4 stores stay 16B-aligned
    __shared__ unsigned As[2][64][20];   // [m][k], stride 20
    __shared__ unsigned Bs[2][16][72];   // [k][n], stride 72 (72 % 32 == 8)

    const int t    = threadIdx.x;
    const int lane = t & 31, warp = t >> 5;
    const int warpM = warp >> 1, warpN = warp & 1;
    const int grp  = lane >> 2, tig = lane & 3;

    // A-tile loader mapping: 2 passes of (32 rows x 4 k-floats)
    const int rA0 = t >> 2;          // 0..31
    const int cA4 = (t & 3) * 4;     // 0,4,8,12
    const float* aptr[2];
    #pragma unroll
    for (int p = 0; p < 2; p++) {
        int m = m0 + rA0 + 32 * p;
        if (GATHER) {
            int tok = (m < cnt) ? g_perm[e * CAP + m] : -1;
            aptr[p] = (tok >= 0) ? (Abase + (size_t)tok * KD) : nullptr;
        } else {
            aptr[p] = Abase + ((size_t)e * CAP + m) * KD;
        }
    }
    // B-tile loader mapping: 2 passes of (8 k-rows x 16 float4 over n)
    const int kB0 = t >> 4;          // 0..7
    const int nB4 = (t & 15) * 4;    // 0..60
    const float* bbase = W + (size_t)e * KD * ND + n0 + nB4;

    float acc[2][4][4];
    #pragma unroll
    for (int i = 0; i < 2; i++)
        #pragma unroll
        for (int j = 0; j < 4; j++)
            #pragma unroll
            for (int q = 0; q < 4; q++) acc[i][j][q] = 0.f;

    const int NT = KD / 16;
    float4 ra[2], rb[2];

    auto loadG = [&](int kt) {
        #pragma unroll
        for (int p = 0; p < 2; p++) {
            if (aptr[p]) ra[p] = *reinterpret_cast<const float4*>(aptr[p] + kt * 16 + cA4);
            else         ra[p] = make_float4(0.f, 0.f, 0.f, 0.f);
        }
        #pragma unroll
        for (int p = 0; p < 2; p++)
            rb[p] = *reinterpret_cast<const float4*>(bbase + (size_t)(kt * 16 + kB0 + 8 * p) * ND);
    };
    auto storeS = [&](int buf) {
        #pragma unroll
        for (int p = 0; p < 2; p++) {
            unsigned* d = &As[buf][rA0 + 32 * p][cA4];
            d[0] = f2tf(ra[p].x); d[1] = f2tf(ra[p].y);
            d[2] = f2tf(ra[p].z); d[3] = f2tf(ra[p].w);
        }
        #pragma unroll
        for (int p = 0; p < 2; p++) {
            unsigned* d = &Bs[buf][kB0 + 8 * p][nB4];
            d[0] = f2tf(rb[p].x); d[1] = f2tf(rb[p].y);
            d[2] = f2tf(rb[p].z); d[3] = f2tf(rb[p].w);
        }
    };

    loadG(0);
    storeS(0);
    __syncthreads();

    for (int kt = 0; kt < NT; kt++) {
        const int buf = kt & 1;
        if (kt + 1 < NT) loadG(kt + 1);

        #pragma unroll
        for (int kk = 0; kk < 2; kk++) {
            unsigned af[2][4], bf[4][2];
            #pragma unroll
            for (int mf = 0; mf < 2; mf++) {
                int mrow = warpM * 32 + mf * 16 + grp;
                int kcol = kk * 8 + tig;
                af[mf][0] = As[buf][mrow    ][kcol    ];
                af[mf][1] = As[buf][mrow + 8][kcol    ];
                af[mf][2] = As[buf][mrow    ][kcol + 4];
                af[mf][3] = As[buf][mrow + 8][kcol + 4];
            }
            #pragma unroll
            for (int nf = 0; nf < 4; nf++) {
                int ncol = warpN * 32 + nf * 8 + grp;
                int krow = kk * 8 + tig;
                bf[nf][0] = Bs[buf][krow    ][ncol];
                bf[nf][1] = Bs[buf][krow + 4][ncol];
            }
            #pragma unroll
            for (int mf = 0; mf < 2; mf++)
                #pragma unroll
                for (int nf = 0; nf < 4; nf++)
                    mma8(acc[mf][nf], af[mf], bf[nf]);
        }

        if (kt + 1 < NT) {
            storeS((kt + 1) & 1);
            __syncthreads();
        }
    }

    // epilogue: + bias, optional exact GELU, write [e*CAP + m, n]
    #pragma unroll
    for (int mf = 0; mf < 2; mf++) {
        #pragma unroll
        for (int nf = 0; nf < 4; nf++) {
            int col = n0 + warpN * 32 + nf * 8 + 2 * tig;
            float bv0 = bias[e * ND + col];
            float bv1 = bias[e * ND + col + 1];
            #pragma unroll
            for (int half = 0; half < 2; half++) {
                int row = m0 + warpM * 32 + mf * 16 + grp + 8 * half;
                float v0 = acc[mf][nf][2 * half + 0] + bv0;
                float v1 = acc[mf][nf][2 * half + 1] + bv1;
                if (GELU_ACT) {
                    v0 = 0.5f * v0 * (1.f + erff(v0 * 0.70710678118654752f));
                    v1 = 0.5f * v1 * (1.f + erff(v1 * 0.70710678118654752f));
                }
                *reinterpret_cast<float2*>(
                    Obase + ((size_t)e * CAP + row) * ND + col) = make_float2(v0, v1);
            }
        }
    }
}

// out[t] = x[t] + w0*y[slot0] + w1*y[slot1]   (no atomics -> deterministic)
__global__ void combine_kernel(const float* __restrict__ x, float* __restrict__ out) {
    const int t = blockIdx.x;
    const int s0 = g_slot[t * 2], s1 = g_slot[t * 2 + 1];
    const float w0 = g_wgt[t * 2], w1 = g_wgt[t * 2 + 1];
    const float4* xr = reinterpret_cast<const float4*>(x + (size_t)t * D_MODEL);
    float4*       orw = reinterpret_cast<float4*>(out + (size_t)t * D_MODEL);
    const float4* y0 = (s0 >= 0) ? reinterpret_cast<const float4*>(g_y + (size_t)s0 * D_MODEL) : nullptr;
    const float4* y1 = (s1 >= 0) ? reinterpret_cast<const float4*>(g_y + (size_t)s1 * D_MODEL) : nullptr;
    const int i = threadIdx.x;               // 256 threads x float4 = 1024 floats
    float4 r = xr[i];
    if (y0) { float4 a = y0[i]; r.x += w0 * a.x; r.y += w0 * a.y; r.z += w0 * a.z; r.w += w0 * a.w; }
    if (y1) { float4 a = y1[i]; r.x += w1 * a.x; r.y += w1 * a.y; r.z += w1 * a.z; r.w += w1 * a.w; }
    orw[i] = r;
}

// ---------------- launch ----------------
extern "C" void kernel_launch(void* const* d_in, const int* in_sizes, int n_in,
                              void* d_out, int out_size) {
    const float* x  = (const float*)d_in[0];
    const float* gw = (const float*)d_in[1];
    const float* gb = (const float*)d_in[2];
    const float* w1 = (const float*)d_in[3];
    const float* b1 = (const float*)d_in[4];
    const float* w2 = (const float*)d_in[5];
    const float* b2 = (const float*)d_in[6];
    float* out = (float*)d_out;

    zero_cnt_kernel<<<1, 32>>>();
    gate_kernel<<<TOKENS, 128>>>(x, gw, gb);

    dim3 g1(D_FF / 64, CAP / 64, NUM_E);      // (64, 8, 24) — inactive M-tiles exit early
    moe_gemm_kernel<D_MODEL, D_FF, true, true><<<g1, 128>>>(x, w1, b1);

    dim3 g2(D_MODEL / 64, CAP / 64, NUM_E);   // (16, 8, 24)
    moe_gemm_kernel<D_FF, D_MODEL, false, false><<<g2, 128>>>(nullptr, w2, b2);

    combine_kernel<<<TOKENS, 256>>>(x, out);
}